// round 1
// baseline (speedup 1.0000x reference)
#include <cuda_runtime.h>
#include <math.h>

#define FULL 0xFFFFFFFFu

static __device__ __forceinline__ float fminf_(float a, float b) { return fminf(a, b); }

#define CH_A 0.955f
#define CH_B 1.3693f
#define CH_INF 1e6f
#define FBIG 3.0e38f

// ---- device scratch (no allocation allowed) ----
__device__ float g_d[16 * 512 * 512];     // distance maps (16 MB, L2-resident)
__device__ float g_dmax[16];
__device__ int   g_hasfg[16];
__device__ float g_acc[50];               // [0]=focal sum, [1]=bnd sum, [2..17]=inter, [18..33]=psum, [34..49]=tsum

__global__ void k_zero() {
    int i = threadIdx.x;
    if (i < 50) g_acc[i] = 0.0f;
}

// ============================================================================
// Chamfer distance transform: one CTA per image, 512 threads (1 per column).
// Shared bitboards for mask/dil/ero/boundary; two row sweeps with block scans.
// ============================================================================
__global__ void k_chamfer(const int* __restrict__ target) {
    extern __shared__ unsigned char smem_raw[];
    unsigned* maskb = (unsigned*)smem_raw;   // 8192 words (512 rows x 16 words)
    unsigned* hdb   = maskb + 8192;
    unsigned* heb   = hdb + 8192;
    unsigned* bdb   = heb + 8192;
    float* prevs    = (float*)(bdb + 8192);  // 514 floats (padded row)
    float* warpmin  = prevs + 514;           // 16 floats

    const int img  = blockIdx.x;
    const int tid  = threadIdx.x;
    const int lane = tid & 31;
    const int wid  = tid >> 5;
    const int* tg  = target + img * (512 * 512);
    float* dimg    = g_d + img * (512 * 512);

    // ---- Phase A: load mask bits (ballot per warp word) ----
    int anyfg = 0;
    #pragma unroll 4
    for (int r = 0; r < 512; ++r) {
        int v = tg[r * 512 + tid];
        unsigned bits = __ballot_sync(FULL, v > 0);
        anyfg |= (v > 0);
        if (lane == 0) maskb[r * 16 + wid] = bits;
    }
    int has_fg = __syncthreads_or(anyfg);

    // ---- Phase B: horizontal dilate / erode per 32-col word ----
    #pragma unroll
    for (int k = 0; k < 16; ++k) {
        int i = tid + k * 512;
        int w = i & 15;
        unsigned cw  = maskb[i];
        unsigned pw  = (w > 0)  ? maskb[i - 1] : 0u;
        unsigned nw_ = (w < 15) ? maskb[i + 1] : 0u;
        unsigned ld = (cw << 1) | (pw >> 31);
        unsigned rd = (cw >> 1) | (nw_ << 31);
        hdb[i] = cw | ld | rd;
        // erosion: out-of-bounds treated as foreground (1)
        unsigned le = (cw << 1) | ((w == 0)  ? 1u          : (pw >> 31));
        unsigned re = (cw >> 1) | ((w == 15) ? 0x80000000u : (nw_ << 31));
        heb[i] = cw & le & re;
    }
    __syncthreads();

    // ---- Phase C: vertical combine -> boundary = dil & ~ero ----
    unsigned anyb = 0;
    #pragma unroll
    for (int k = 0; k < 16; ++k) {
        int i = tid + k * 512;
        int r = i >> 4;
        unsigned dil = hdb[i];
        unsigned ero = heb[i];
        if (r > 0)   { dil |= hdb[i - 16]; ero &= heb[i - 16]; }
        if (r < 511) { dil |= hdb[i + 16]; ero &= heb[i + 16]; }
        unsigned bd = dil & ~ero;
        bdb[i] = bd;
        anyb |= bd;
    }
    int has_b = __syncthreads_or(anyb != 0);

    // ---- Phase D: seeds = has_b ? boundary : ~mask  (stored in maskb) ----
    #pragma unroll
    for (int k = 0; k < 16; ++k) {
        int i = tid + k * 512;
        maskb[i] = has_b ? bdb[i] : ~maskb[i];
    }

    // init prev row to INF (padded)
    prevs[tid + 1] = CH_INF;
    if (tid < 2) prevs[tid * 513] = CH_INF;  // prevs[0], prevs[513]
    __syncthreads();

    const float jf = (float)tid;

    // ---- Forward sweep (top-left -> bottom-right) ----
    for (int r = 0; r < 512; ++r) {
        unsigned sw = maskb[r * 16 + wid];
        float d0 = ((sw >> lane) & 1u) ? 0.0f : CH_INF;
        float pl = prevs[tid];
        float pc = prevs[tid + 1];
        float pr = prevs[tid + 2];
        float m = fminf_(fminf_(d0, pc + CH_A), fminf_(pl + CH_B, pr + CH_B));
        float v = m - CH_A * jf;
        // warp inclusive prefix-min (left -> right)
        #pragma unroll
        for (int o = 1; o < 32; o <<= 1) {
            float t = __shfl_up_sync(FULL, v, o);
            if (lane >= o) v = fminf_(v, t);
        }
        float agg = __shfl_sync(FULL, v, 31);
        if (lane == 0) warpmin[wid] = agg;
        __syncthreads();
        // cross-warp offset: min over warps < wid (ILP tree)
        float w[16];
        #pragma unroll
        for (int k = 0; k < 16; ++k) w[k] = (k < wid) ? warpmin[k] : FBIG;
        #pragma unroll
        for (int s = 8; s >= 1; s >>= 1) {
            #pragma unroll
            for (int k2 = 0; k2 < 8; ++k2)
                if (k2 < s) w[k2] = fminf_(w[k2], w[k2 + s]);
        }
        v = fminf_(v, w[0]);
        float cur = CH_A * jf + v;
        prevs[tid + 1] = cur;
        dimg[r * 512 + tid] = cur;
        __syncthreads();
    }

    // re-init prev row
    prevs[tid + 1] = CH_INF;
    if (tid < 2) prevs[tid * 513] = CH_INF;
    __syncthreads();

    const float rjf = (float)(511 - tid);
    float dmx = 0.0f;

    // ---- Backward sweep (bottom-right -> top-left), prefetched rows ----
    float dload = dimg[511 * 512 + tid];
    for (int r = 511; r >= 0; --r) {
        float d0 = dload;
        if (r > 0) dload = dimg[(r - 1) * 512 + tid];  // prefetch next row (L2)
        float pl = prevs[tid];
        float pc = prevs[tid + 1];
        float pr = prevs[tid + 2];
        float m = fminf_(fminf_(d0, pc + CH_A), fminf_(pl + CH_B, pr + CH_B));
        float v = m - CH_A * rjf;
        // warp inclusive suffix-min (right -> left)
        #pragma unroll
        for (int o = 1; o < 32; o <<= 1) {
            float t = __shfl_down_sync(FULL, v, o);
            if (lane + o < 32) v = fminf_(v, t);
        }
        float agg = __shfl_sync(FULL, v, 0);
        if (lane == 0) warpmin[wid] = agg;
        __syncthreads();
        // cross-warp offset: min over warps > wid
        float w[16];
        #pragma unroll
        for (int k = 0; k < 16; ++k) w[k] = (k > wid) ? warpmin[k] : FBIG;
        #pragma unroll
        for (int s = 8; s >= 1; s >>= 1) {
            #pragma unroll
            for (int k2 = 0; k2 < 8; ++k2)
                if (k2 < s) w[k2] = fminf_(w[k2], w[k2 + s]);
        }
        v = fminf_(v, w[0]);
        float cur = CH_A * rjf + v;
        dmx = fmaxf(dmx, cur);
        prevs[tid + 1] = cur;
        dimg[r * 512 + tid] = cur;
        __syncthreads();
    }

    // ---- block max-reduce of final distance map ----
    #pragma unroll
    for (int o = 16; o >= 1; o >>= 1) dmx = fmaxf(dmx, __shfl_xor_sync(FULL, dmx, o));
    if (lane == 0) warpmin[wid] = dmx;
    __syncthreads();
    if (tid == 0) {
        float mx = warpmin[0];
        #pragma unroll
        for (int k = 1; k < 16; ++k) mx = fmaxf(mx, warpmin[k]);
        g_dmax[img] = mx;
        g_hasfg[img] = has_fg;
    }
}

// ============================================================================
// Elementwise losses + reductions. 256 blocks x 256 threads, float4 streams.
// ============================================================================
__global__ void k_losses(const float* __restrict__ pred, const int* __restrict__ target) {
    const int img   = blockIdx.x >> 4;
    const int chunk = blockIdx.x & 15;
    const int base  = img * (512 * 512) + chunk * 16384;
    const int tid   = threadIdx.x;  // 256

    float mx  = g_dmax[img];
    float inv = (mx > 0.0f) ? (1.0f / fmaxf(mx, 1e-12f)) : 1.0f;
    int hfg   = g_hasfg[img];

    float s_focal = 0.f, s_bnd = 0.f, s_i = 0.f, s_p = 0.f, s_t = 0.f;

    #pragma unroll 4
    for (int k = 0; k < 16; ++k) {
        int i = base + (k * 256 + tid) * 4;
        float4 x4 = *(const float4*)(pred + i);
        int4   t4 = *(const int4*)(target + i);
        float4 d4 = *(const float4*)(g_d + i);
        #pragma unroll
        for (int e = 0; e < 4; ++e) {
            float x   = (&x4.x)[e];
            int   tgi = (&t4.x)[e];
            float dd  = (&d4.x)[e];
            float t = (float)tgi;
            float ax = fabsf(x);
            float ee = expf(-ax);
            float l  = log1pf(ee);
            float lsp = (x >= 0.f) ? -l : (x - l);       // log sigmoid(x)
            float lsn = (x >= 0.f) ? (-x - l) : -l;      // log sigmoid(-x)
            float bce = -(t * lsp + (1.f - t) * lsn);
            float p = (x >= 0.f) ? (1.f / (1.f + ee)) : (ee / (1.f + ee));
            float pt = tgi ? p : (1.f - p);
            float at = tgi ? 0.25f : 0.75f;
            float om = 1.f - pt;
            s_focal += at * om * om * bce;
            s_i += p * t;
            s_p += p;
            s_t += t;
            float dn = dd * inv;
            float dist = hfg ? dn : 1.0f;
            s_bnd += (t * (1.f - p) + (1.f - t) * p) * (1.f + dist);
        }
    }

    // block reduce (warp shfl + shared), one atomic per block per quantity
    #pragma unroll
    for (int o = 16; o >= 1; o >>= 1) {
        s_focal += __shfl_xor_sync(FULL, s_focal, o);
        s_bnd   += __shfl_xor_sync(FULL, s_bnd, o);
        s_i     += __shfl_xor_sync(FULL, s_i, o);
        s_p     += __shfl_xor_sync(FULL, s_p, o);
        s_t     += __shfl_xor_sync(FULL, s_t, o);
    }
    __shared__ float red[8][5];
    int lane = tid & 31, wid = tid >> 5;
    if (lane == 0) { red[wid][0]=s_focal; red[wid][1]=s_bnd; red[wid][2]=s_i; red[wid][3]=s_p; red[wid][4]=s_t; }
    __syncthreads();
    if (tid == 0) {
        float a0=0,a1=0,a2=0,a3=0,a4=0;
        #pragma unroll
        for (int k = 0; k < 8; ++k) { a0+=red[k][0]; a1+=red[k][1]; a2+=red[k][2]; a3+=red[k][3]; a4+=red[k][4]; }
        atomicAdd(&g_acc[0], a0);
        atomicAdd(&g_acc[1], a1);
        atomicAdd(&g_acc[2 + img], a2);
        atomicAdd(&g_acc[18 + img], a3);
        atomicAdd(&g_acc[34 + img], a4);
    }
}

// ============================================================================
// Final combine
// ============================================================================
__global__ void k_final(const float* __restrict__ log_vars, float* __restrict__ out) {
    if (threadIdx.x != 0) return;
    const float N = 16.0f * 512.0f * 512.0f;
    float focal = g_acc[0] / N;
    float bnd   = g_acc[1] / N;
    float dsum = 0.f, isum = 0.f;
    #pragma unroll
    for (int b = 0; b < 16; ++b) {
        float I = g_acc[2 + b];
        float T = g_acc[18 + b] + g_acc[34 + b];
        dsum += (2.0f * I + 1e-6f) / (T + 1e-6f);
        isum += (I + 1e-6f) / (T - I + 1e-6f);
    }
    float dice = 1.0f - dsum / 16.0f;
    float iou  = 1.0f - isum / 16.0f;
    float lv0 = log_vars[0], lv1 = log_vars[1], lv2 = log_vars[2], lv3 = log_vars[3];
    float total = expf(-lv0) * focal + lv0
                + expf(-lv1) * dice  + lv1
                + expf(-lv2) * bnd   + lv2
                + expf(-lv3) * iou   + lv3;
    out[0] = total; out[1] = focal; out[2] = dice; out[3] = bnd; out[4] = iou;
}

extern "C" void kernel_launch(void* const* d_in, const int* in_sizes, int n_in,
                              void* d_out, int out_size) {
    const float* pred     = (const float*)d_in[0];
    const int*   target   = (const int*)d_in[1];
    const float* log_vars = (const float*)d_in[2];
    float* out = (float*)d_out;

    const size_t smem = 4 * 8192 * sizeof(unsigned) + (514 + 16) * sizeof(float);
    cudaFuncSetAttribute(k_chamfer, cudaFuncAttributeMaxDynamicSharedMemorySize, (int)smem);

    k_zero<<<1, 64>>>();
    k_chamfer<<<16, 512, smem>>>(target);
    k_losses<<<256, 256>>>(pred, target);
    k_final<<<1, 32>>>(log_vars, out);
}

// round 4
// speedup vs baseline: 1.8737x; 1.8737x over previous
#include <cuda_runtime.h>
#include <math.h>

#define FULL 0xFFFFFFFFu

#define CH_A 0.955f
#define CH_B 1.3693f
#define CH_INF 1e6f

// ---- device scratch (no allocation allowed) ----
__device__ float    g_d[16 * 512 * 512];   // distance maps (16 MB, L2-resident)
__device__ unsigned g_seed[16 * 8192];     // seed bitboards
__device__ float    g_dmax[16];
__device__ int      g_hasfg[16];
__device__ float    g_acc[50];             // [0]=focal, [1]=bnd, [2..17]=inter, [18..33]=psum, [34..49]=tsum

__global__ void k_zero() {
    int i = threadIdx.x;
    if (i < 50) g_acc[i] = 0.0f;
}

// ============================================================================
// Seed construction: one CTA per image, 512 threads. Bitboard morphology.
// ============================================================================
__global__ void k_seeds(const int* __restrict__ target) {
    extern __shared__ unsigned char smem_raw[];
    unsigned* maskb = (unsigned*)smem_raw;   // 8192 words (512 rows x 16 words)
    unsigned* hdb   = maskb + 8192;
    unsigned* heb   = hdb + 8192;
    unsigned* bdb   = heb + 8192;

    const int img  = blockIdx.x;
    const int tid  = threadIdx.x;
    const int lane = tid & 31;
    const int wid  = tid >> 5;
    const int* tg  = target + img * (512 * 512);

    // ---- Phase A: load mask bits (ballot per warp word) ----
    int anyfg = 0;
    #pragma unroll 8
    for (int r = 0; r < 512; ++r) {
        int v = tg[r * 512 + tid];
        unsigned bits = __ballot_sync(FULL, v > 0);
        anyfg |= (v > 0);
        if (lane == 0) maskb[r * 16 + wid] = bits;
    }
    int has_fg = __syncthreads_or(anyfg);

    // ---- Phase B: horizontal dilate / erode per 32-col word ----
    #pragma unroll
    for (int k = 0; k < 16; ++k) {
        int i = tid + k * 512;
        int w = i & 15;
        unsigned cw  = maskb[i];
        unsigned pw  = (w > 0)  ? maskb[i - 1] : 0u;
        unsigned nw_ = (w < 15) ? maskb[i + 1] : 0u;
        unsigned ld = (cw << 1) | (pw >> 31);
        unsigned rd = (cw >> 1) | (nw_ << 31);
        hdb[i] = cw | ld | rd;
        // erosion: out-of-bounds treated as foreground (1)
        unsigned le = (cw << 1) | ((w == 0)  ? 1u          : (pw >> 31));
        unsigned re = (cw >> 1) | ((w == 15) ? 0x80000000u : (nw_ << 31));
        heb[i] = cw & le & re;
    }
    __syncthreads();

    // ---- Phase C: vertical combine -> boundary = dil & ~ero ----
    unsigned anyb = 0;
    #pragma unroll
    for (int k = 0; k < 16; ++k) {
        int i = tid + k * 512;
        int r = i >> 4;
        unsigned dil = hdb[i];
        unsigned ero = heb[i];
        if (r > 0)   { dil |= hdb[i - 16]; ero &= heb[i - 16]; }
        if (r < 511) { dil |= hdb[i + 16]; ero &= heb[i + 16]; }
        unsigned bd = dil & ~ero;
        bdb[i] = bd;
        anyb |= bd;
    }
    int has_b = __syncthreads_or(anyb != 0);

    // ---- Phase D: seeds = has_b ? boundary : ~mask -> global ----
    unsigned* gs = g_seed + img * 8192;
    #pragma unroll
    for (int k = 0; k < 16; ++k) {
        int i = tid + k * 512;
        gs[i] = has_b ? bdb[i] : ~maskb[i];
    }
    if (tid == 0) g_hasfg[img] = has_fg;
}

// ============================================================================
// Chamfer sweeps: ONE WARP per image. 16 columns per thread, all in registers,
// tilted coordinates u = d - A*j. Zero barriers in the row loop.
// ============================================================================
__global__ void __launch_bounds__(32) k_sweep() {
    __shared__ unsigned sb[8192];
    const int img  = blockIdx.x;
    const int lane = threadIdx.x;
    const unsigned* gs = g_seed + img * 8192;
    float* dimg = g_d + img * (512 * 512);

    // copy seed board to shared (64 uint4 per thread)
    #pragma unroll
    for (int k = 0; k < 64; ++k) {
        int i = (k * 32 + lane) * 4;
        *(uint4*)(sb + i) = *(const uint4*)(gs + i);
    }
    __syncwarp();

    const int c0 = lane * 16;
    float sc[16], u[16];
    #pragma unroll
    for (int j = 0; j < 16; ++j) {
        sc[j] = -CH_A * (float)(c0 + j);   // tilted seed value: 0 - A*j
        u[j]  = CH_INF;
    }

    // ================= Pass 1: top -> bottom, left -> right =================
    for (int r = 0; r < 512; ++r) {
        unsigned wv   = sb[(r << 4) + (lane >> 1)];
        unsigned bits = wv >> ((lane & 1) << 4);
        float uL = __shfl_up_sync(FULL, u[15], 1); if (lane == 0)  uL = CH_INF;
        float uR = __shfl_down_sync(FULL, u[0], 1); if (lane == 31) uR = CH_INF;
        float v[16];
        #pragma unroll
        for (int j = 0; j < 16; ++j) {
            float left  = (j == 0)  ? uL : u[j - 1];
            float right = (j == 15) ? uR : u[j + 1];
            float a = fminf(u[j] + CH_A, left + (CH_B - CH_A));
            float m = fminf(a, right + (CH_B + CH_A));
            if ((bits >> j) & 1u) m = fminf(m, sc[j]);
            v[j] = m;
        }
        // in-thread inclusive prefix-min
        float s = v[0]; u[0] = s;
        #pragma unroll
        for (int j = 1; j < 16; ++j) { s = fminf(s, v[j]); u[j] = s; }
        // warp Kogge-Stone inclusive on thread totals, then exclusive shift
        float inc = s;
        #pragma unroll
        for (int o = 1; o < 32; o <<= 1) {
            float t = __shfl_up_sync(FULL, inc, o);
            if (lane >= o) inc = fminf(inc, t);
        }
        float exc = __shfl_up_sync(FULL, inc, 1);
        if (lane == 0) exc = CH_INF;
        #pragma unroll
        for (int j = 0; j < 16; ++j) u[j] = fminf(u[j], exc);
        // store tilted row
        float* row = dimg + r * 512 + c0;
        #pragma unroll
        for (int k = 0; k < 4; ++k)
            *(float4*)(row + 4 * k) = make_float4(u[4*k], u[4*k+1], u[4*k+2], u[4*k+3]);
    }

    // ================= Pass 2: bottom -> top, right -> left =================
    // pass-2 tilt: u2[j] = d[j] - A*(511-j). d0 (pass-1 result, stored tilted by
    // -A*j) converts via + A*(2j-511). Output d = u2 + A*(511-j).
    float c2[16], co[16];
    #pragma unroll
    for (int j = 0; j < 16; ++j) {
        c2[j] = CH_A * (float)(2 * (c0 + j) - 511);
        co[j] = CH_A * (float)(511 - (c0 + j));
        u[j]  = CH_INF;
    }
    float nx[16];
    {
        const float* rowp = dimg + 511 * 512 + c0;
        #pragma unroll
        for (int k = 0; k < 4; ++k) {
            float4 t4 = *(const float4*)(rowp + 4 * k);
            nx[4*k] = t4.x; nx[4*k+1] = t4.y; nx[4*k+2] = t4.z; nx[4*k+3] = t4.w;
        }
    }
    float dmx = 0.0f;
    for (int r = 511; r >= 0; --r) {
        float uL = __shfl_up_sync(FULL, u[15], 1); if (lane == 0)  uL = CH_INF;
        float uR = __shfl_down_sync(FULL, u[0], 1); if (lane == 31) uR = CH_INF;
        float v[16];
        #pragma unroll
        for (int j = 0; j < 16; ++j) {
            float left  = (j == 0)  ? uL : u[j - 1];
            float right = (j == 15) ? uR : u[j + 1];
            float a = fminf(u[j] + CH_A, right + (CH_B - CH_A));  // diag flip vs pass 1
            float b = fminf(left + (CH_B + CH_A), nx[j] + c2[j]);
            v[j] = fminf(a, b);
        }
        // prefetch next pass-1 row (same thread wrote it; L1/L2 hit)
        if (r > 0) {
            const float* rowp = dimg + (r - 1) * 512 + c0;
            #pragma unroll
            for (int k = 0; k < 4; ++k) {
                float4 t4 = *(const float4*)(rowp + 4 * k);
                nx[4*k] = t4.x; nx[4*k+1] = t4.y; nx[4*k+2] = t4.z; nx[4*k+3] = t4.w;
            }
        }
        // in-thread inclusive suffix-min (right -> left)
        float s = v[15]; u[15] = s;
        #pragma unroll
        for (int j = 14; j >= 0; --j) { s = fminf(s, v[j]); u[j] = s; }
        // warp scan over lanes above
        float inc = s;
        #pragma unroll
        for (int o = 1; o < 32; o <<= 1) {
            float t = __shfl_down_sync(FULL, inc, o);
            if (lane + o < 32) inc = fminf(inc, t);
        }
        float exc = __shfl_down_sync(FULL, inc, 1);
        if (lane == 31) exc = CH_INF;
        float out[16];
        #pragma unroll
        for (int j = 0; j < 16; ++j) {
            float uu = fminf(u[j], exc);
            u[j] = uu;
            float d = uu + co[j];           // untilt -> final distance
            out[j] = d;
            dmx = fmaxf(dmx, d);
        }
        float* row = dimg + r * 512 + c0;
        #pragma unroll
        for (int k = 0; k < 4; ++k)
            *(float4*)(row + 4 * k) = make_float4(out[4*k], out[4*k+1], out[4*k+2], out[4*k+3]);
    }

    #pragma unroll
    for (int o = 16; o >= 1; o >>= 1) dmx = fmaxf(dmx, __shfl_xor_sync(FULL, dmx, o));
    if (lane == 0) g_dmax[img] = dmx;
}

// ============================================================================
// Elementwise losses + reductions. 1024 blocks x 256 threads, float4 streams.
// ============================================================================
__global__ void k_losses(const float* __restrict__ pred, const int* __restrict__ target) {
    const int img   = blockIdx.x >> 6;
    const int chunk = blockIdx.x & 63;
    const int base  = img * (512 * 512) + chunk * 4096;
    const int tid   = threadIdx.x;  // 256

    float mx  = g_dmax[img];
    float inv = (mx > 0.0f) ? (1.0f / fmaxf(mx, 1e-12f)) : 1.0f;
    int hfg   = g_hasfg[img];

    float s_focal = 0.f, s_bnd = 0.f, s_i = 0.f, s_p = 0.f, s_t = 0.f;

    #pragma unroll
    for (int k = 0; k < 4; ++k) {
        int i = base + (k * 256 + tid) * 4;
        float4 x4 = *(const float4*)(pred + i);
        int4   t4 = *(const int4*)(target + i);
        float4 d4 = *(const float4*)(g_d + i);
        #pragma unroll
        for (int e = 0; e < 4; ++e) {
            float x   = (&x4.x)[e];
            int   tgi = (&t4.x)[e];
            float dd  = (&d4.x)[e];
            float t = (float)tgi;
            float ax = fabsf(x);
            float ee = expf(-ax);
            float l  = log1pf(ee);
            float lsp = (x >= 0.f) ? -l : (x - l);       // log sigmoid(x)
            float lsn = (x >= 0.f) ? (-x - l) : -l;      // log sigmoid(-x)
            float bce = -(t * lsp + (1.f - t) * lsn);
            float p = (x >= 0.f) ? (1.f / (1.f + ee)) : (ee / (1.f + ee));
            float pt = tgi ? p : (1.f - p);
            float at = tgi ? 0.25f : 0.75f;
            float om = 1.f - pt;
            s_focal += at * om * om * bce;
            s_i += p * t;
            s_p += p;
            s_t += t;
            float dn = dd * inv;
            float dist = hfg ? dn : 1.0f;
            s_bnd += (t * (1.f - p) + (1.f - t) * p) * (1.f + dist);
        }
    }

    #pragma unroll
    for (int o = 16; o >= 1; o >>= 1) {
        s_focal += __shfl_xor_sync(FULL, s_focal, o);
        s_bnd   += __shfl_xor_sync(FULL, s_bnd, o);
        s_i     += __shfl_xor_sync(FULL, s_i, o);
        s_p     += __shfl_xor_sync(FULL, s_p, o);
        s_t     += __shfl_xor_sync(FULL, s_t, o);
    }
    __shared__ float red[8][5];
    int lane = tid & 31, wid = tid >> 5;
    if (lane == 0) { red[wid][0]=s_focal; red[wid][1]=s_bnd; red[wid][2]=s_i; red[wid][3]=s_p; red[wid][4]=s_t; }
    __syncthreads();
    if (tid == 0) {
        float a0=0,a1=0,a2=0,a3=0,a4=0;
        #pragma unroll
        for (int k = 0; k < 8; ++k) { a0+=red[k][0]; a1+=red[k][1]; a2+=red[k][2]; a3+=red[k][3]; a4+=red[k][4]; }
        atomicAdd(&g_acc[0], a0);
        atomicAdd(&g_acc[1], a1);
        atomicAdd(&g_acc[2 + img], a2);
        atomicAdd(&g_acc[18 + img], a3);
        atomicAdd(&g_acc[34 + img], a4);
    }
}

// ============================================================================
// Final combine
// ============================================================================
__global__ void k_final(const float* __restrict__ log_vars, float* __restrict__ out) {
    if (threadIdx.x != 0) return;
    const float N = 16.0f * 512.0f * 512.0f;
    float focal = g_acc[0] / N;
    float bnd   = g_acc[1] / N;
    float dsum = 0.f, isum = 0.f;
    #pragma unroll
    for (int b = 0; b < 16; ++b) {
        float I = g_acc[2 + b];
        float T = g_acc[18 + b] + g_acc[34 + b];
        dsum += (2.0f * I + 1e-6f) / (T + 1e-6f);
        isum += (I + 1e-6f) / (T - I + 1e-6f);
    }
    float dice = 1.0f - dsum / 16.0f;
    float iou  = 1.0f - isum / 16.0f;
    float lv0 = log_vars[0], lv1 = log_vars[1], lv2 = log_vars[2], lv3 = log_vars[3];
    float total = expf(-lv0) * focal + lv0
                + expf(-lv1) * dice  + lv1
                + expf(-lv2) * bnd   + lv2
                + expf(-lv3) * iou   + lv3;
    out[0] = total; out[1] = focal; out[2] = dice; out[3] = bnd; out[4] = iou;
}

extern "C" void kernel_launch(void* const* d_in, const int* in_sizes, int n_in,
                              void* d_out, int out_size) {
    const float* pred     = (const float*)d_in[0];
    const int*   target   = (const int*)d_in[1];
    const float* log_vars = (const float*)d_in[2];
    float* out = (float*)d_out;

    const size_t smem = 4 * 8192 * sizeof(unsigned);
    cudaFuncSetAttribute(k_seeds, cudaFuncAttributeMaxDynamicSharedMemorySize, (int)smem);

    k_zero<<<1, 64>>>();
    k_seeds<<<16, 512, smem>>>(target);
    k_sweep<<<16, 32>>>();
    k_losses<<<1024, 256>>>(pred, target);
    k_final<<<1, 32>>>(log_vars, out);
}